// round 8
// baseline (speedup 1.0000x reference)
#include <cuda_runtime.h>
#include <math.h>

#define T_LEN 512
#define BATCH 64
#define HID   512
#define BH    (BATCH * HID)
#define WPITCH0 516            // op0 weight pitch: mod 32 = 4 -> conflict-free B-frag LDS
#define BPITCH 20              // stage pitch: mod 32 = 20 -> conflict-free A-frag LDS
#define BUFSZ  (64 * BPITCH)   // 1280 floats per chunk buffer
#define NBUF   2               // staging depth per warp
#define PPITCH 33              // partials pitch

// ---------------------------------------------------------------------------
// Static device scratch
// ---------------------------------------------------------------------------
__device__ float g_xr[(size_t)BATCH * T_LEN * HID];     // tf32-rounded x
__device__ float g_hseq[(size_t)T_LEN * BH];            // layer-0 hidden sequence (tf32)
__device__ float g_h2[2 * BH];                          // layer-1 hidden double buffer (tf32)
__device__ unsigned g_flag[2 * T_LEN * 64];             // per-(layer,step,producer) flags

// ---------------------------------------------------------------------------
// TF32 + MMA helpers
// ---------------------------------------------------------------------------
__device__ __forceinline__ unsigned f2tf(float f) {
    unsigned u;
    asm("cvt.rna.tf32.f32 %0, %1;" : "=r"(u) : "f"(f));
    return u;
}
__device__ __forceinline__ float tfr(float f) { return __uint_as_float(f2tf(f)); }

__device__ __forceinline__ void mma_m16n8k8(float c[4], const unsigned a[4], const unsigned b[2]) {
    asm volatile(
        "mma.sync.aligned.m16n8k8.row.col.f32.tf32.tf32.f32 "
        "{%0,%1,%2,%3}, {%4,%5,%6,%7}, {%8,%9}, {%0,%1,%2,%3};"
        : "+f"(c[0]), "+f"(c[1]), "+f"(c[2]), "+f"(c[3])
        : "r"(a[0]), "r"(a[1]), "r"(a[2]), "r"(a[3]), "r"(b[0]), "r"(b[1]));
}

// Gate-interleaved column n = 4*j + gate -> original weight row r = gate*512 + j
__device__ __forceinline__ int remap_row(int n) { return ((n & 3) << 9) | (n >> 2); }

__device__ __forceinline__ void cp_commit() {
    asm volatile("cp.async.commit_group;" ::: "memory");
}
__device__ __forceinline__ void cp_wait0() { asm volatile("cp.async.wait_group 0;" ::: "memory"); }
__device__ __forceinline__ void cp_wait1() { asm volatile("cp.async.wait_group 1;" ::: "memory"); }

// Warp-coalesced 8-flag wait: lanes 0..7 load 8 contiguous flag words
// (one 32B L2 request per poll), ballot, nanosleep backoff on miss.
__device__ __forceinline__ void spin8(const unsigned* base) {
    const int lane = threadIdx.x & 31;
    for (;;) {
        unsigned v = 1u;
        if (lane < 8)
            asm volatile("ld.acquire.gpu.global.u32 %0, [%1];"
                         : "=r"(v) : "l"(base + lane));
        if (__all_sync(0xffffffffu, v != 0u)) break;
        __nanosleep(200);
    }
}

// Issue one warp-private 64x16 chunk (64 rows x 64 B) via cp.async.cg.
__device__ __forceinline__ void issue_chunk(float* buf, const float* __restrict__ src,
                                            size_t stride, int col0, int lane) {
#pragma unroll
    for (int i = 0; i < 8; i++) {
        int cc = lane + (i << 5);
        int row = cc >> 2, c4 = (cc & 3) << 2;
        const float* g = src + (size_t)row * stride + col0 + c4;
        unsigned s = (unsigned)__cvta_generic_to_shared(buf + row * BPITCH + c4);
        asm volatile("cp.async.cg.shared.global [%0], [%1], 16;" :: "r"(s), "l"(g));
    }
}

// MMA over one 16-wide K chunk with B from SMEM (op0 path).
__device__ __forceinline__ void mma_chunk_smemB(float acc[4][4][4], const float* buf,
                                                const float* sW0, int kbase,
                                                int gi, int ti) {
#pragma unroll
    for (int kc = 0; kc < 2; kc++) {
        int kl = kc << 3;
        unsigned afr[4][4];
#pragma unroll
        for (int mt = 0; mt < 4; mt++) {
            int r = mt * 16;
            afr[mt][0] = __float_as_uint(buf[(r + gi) * BPITCH + kl + ti]);
            afr[mt][1] = __float_as_uint(buf[(r + gi + 8) * BPITCH + kl + ti]);
            afr[mt][2] = __float_as_uint(buf[(r + gi) * BPITCH + kl + ti + 4]);
            afr[mt][3] = __float_as_uint(buf[(r + gi + 8) * BPITCH + kl + ti + 4]);
        }
#pragma unroll
        for (int nt = 0; nt < 4; nt++) {
            unsigned bfr[2];
            bfr[0] = __float_as_uint(sW0[(nt * 8 + gi) * WPITCH0 + kbase + kl + ti]);
            bfr[1] = __float_as_uint(sW0[(nt * 8 + gi) * WPITCH0 + kbase + kl + ti + 4]);
#pragma unroll
            for (int mt = 0; mt < 4; mt++) mma_m16n8k8(acc[mt][nt], afr[mt], bfr);
        }
    }
}

// MMA over one 16-wide K chunk with B from registers (op1 / critical path).
__device__ __forceinline__ void mma_chunk_regB(float acc[4][4][4], const float* buf,
                                               const unsigned breg[4][8][2], int cidx,
                                               int gi, int ti) {
#pragma unroll
    for (int kc = 0; kc < 2; kc++) {
        int kl = kc << 3;
        int kk = (cidx << 1) + kc;
        unsigned afr[4][4];
#pragma unroll
        for (int mt = 0; mt < 4; mt++) {
            int r = mt * 16;
            afr[mt][0] = __float_as_uint(buf[(r + gi) * BPITCH + kl + ti]);
            afr[mt][1] = __float_as_uint(buf[(r + gi + 8) * BPITCH + kl + ti]);
            afr[mt][2] = __float_as_uint(buf[(r + gi) * BPITCH + kl + ti + 4]);
            afr[mt][3] = __float_as_uint(buf[(r + gi + 8) * BPITCH + kl + ti + 4]);
        }
#pragma unroll
        for (int nt = 0; nt < 4; nt++)
#pragma unroll
            for (int mt = 0; mt < 4; mt++)
                mma_m16n8k8(acc[mt][nt], afr[mt], breg[nt][kk]);
    }
}

__device__ __forceinline__ float fsig(float x) {
    return __fdividef(1.f, 1.f + __expf(-x));
}
__device__ __forceinline__ float ftanh(float x) {
    return 1.f - __fdividef(2.f, __expf(2.f * x) + 1.f);
}

// ---------------------------------------------------------------------------
// Fused dual-layer persistent LSTM.
// 128 blocks (64/layer), 256 threads (8 warps). Block owns 32 interleaved
// gate cols. Per-producer flag words (st.release / coalesced acquire-poll).
// Warp-private cp.async staging depth 2 with issue-after-mma; L0 carries
// next-step x chunks over the step boundary. 2 syncthreads per step.
// ---------------------------------------------------------------------------
extern "C" __global__ void __launch_bounds__(256, 1)
lstm_fused(const float* __restrict__ Wx0, const float* __restrict__ bx0,
           const float* __restrict__ Wh0, const float* __restrict__ bh0,
           const float* __restrict__ Wx1, const float* __restrict__ bx1,
           const float* __restrict__ Wh1, const float* __restrict__ bh1,
           float* __restrict__ out) {
    extern __shared__ float smem[];
    float* sW0 = smem;                          // 32*WPITCH0 = 16512 floats
    float* sStage = smem + 32 * WPITCH0;        // 8*NBUF*BUFSZ = 20480 floats
    float* sP = sStage + 8 * NBUF * BUFSZ;      // 16896 floats (dedicated partials)
    float* sC = sP + 8 * 64 * PPITCH;           // 512
    float* sBias = sC + 512;                    // 32

    const int tid = threadIdx.x;
    const int w = tid >> 5;
    const int lane = tid & 31;
    const int gi = lane >> 2;
    const int ti = lane & 3;
    const int layer = blockIdx.x >> 6;
    const int bslot = blockIdx.x & 63;
    const int n_blk = bslot * 32;
    const int kw = w * 64;                      // warp K-slice base within an operand

    float* buf0 = sStage + (w * NBUF) * BUFSZ;
    float* buf1 = buf0 + BUFSZ;

    // op0 weight matrix -> SMEM ; op1 weight matrix -> registers
    const float* W0 = layer ? Wh1 : Wx0;   // op0: L0=x·Wx0, L1=h2·Wh1
    const float* W1 = layer ? Wx1 : Wh0;   // op1: L0=h1·Wh0, L1=h1·Wx1
    const float* bxp = layer ? bx1 : bx0;
    const float* bhp = layer ? bh1 : bh0;

    // Stage op0 weights once (remapped rows, tf32-rounded)
    for (int v = tid; v < 32 * 128; v += 256) {
        int row = v >> 7, c4 = (v & 127) * 4;
        int r = remap_row(n_blk + row);
        float4 f = *(const float4*)(W0 + (size_t)r * 512 + c4);
        float* d = sW0 + (size_t)row * WPITCH0 + c4;
        d[0] = tfr(f.x); d[1] = tfr(f.y); d[2] = tfr(f.z); d[3] = tfr(f.w);
    }
    if (tid < 32) {
        int r = remap_row(n_blk + tid);
        sBias[tid] = bxp[r] + bhp[r];
    }
    for (int v = tid; v < 512; v += 256) sC[v] = 0.f;

    // Preload op1 B-fragments into registers (constant across all steps)
    unsigned breg[4][8][2];
#pragma unroll
    for (int nt = 0; nt < 4; nt++) {
        int r = remap_row(n_blk + nt * 8 + gi);
        const float* wr = W1 + (size_t)r * 512 + kw + ti;
#pragma unroll
        for (int kc = 0; kc < 8; kc++) {
            breg[nt][kc][0] = f2tf(wr[kc * 8]);
            breg[nt][kc][1] = f2tf(wr[kc * 8 + 4]);
        }
    }
    __syncthreads();

    // L0: prime chunks 0,1 of t=0 op0 (x); steady state carries these over.
    if (layer == 0) {
        issue_chunk(buf0, g_xr, (size_t)T_LEN * HID, kw + 0, lane);
        cp_commit();
        issue_chunk(buf1, g_xr, (size_t)T_LEN * HID, kw + 16, lane);
        cp_commit();
    }

    for (int t = 0; t < T_LEN; t++) {
        float acc[4][4][4];
#pragma unroll
        for (int a = 0; a < 4; a++)
#pragma unroll
            for (int b = 0; b < 4; b++)
#pragma unroll
                for (int c = 0; c < 4; c++) acc[a][b][c] = 0.f;

        const float* srcs[2];
        size_t strds[2];
        bool vals[2];
        if (layer == 0) {
            srcs[0] = g_xr + (size_t)t * 512;            // x[b][t][:]
            strds[0] = (size_t)T_LEN * HID;  vals[0] = true;
            srcs[1] = g_hseq + (size_t)(t - 1) * BH;
            strds[1] = HID;                  vals[1] = (t > 0);
        } else {
            srcs[0] = g_h2 + (size_t)((t + 1) & 1) * BH;
            strds[0] = HID;                  vals[0] = (t > 0);
            srcs[1] = g_hseq + (size_t)t * BH;
            strds[1] = HID;                  vals[1] = true;
        }

        // L1 step start: wait own-cohort group flags (t-1), then issue c0,c1.
        if (layer == 1) {
            if (t > 0) {
                spin8(&g_flag[(size_t)(T_LEN + (t - 1)) * 64 + 8 * w]);
                issue_chunk(buf0, srcs[0], strds[0], kw + 0, lane);
                issue_chunk(buf1, srcs[0], strds[0], kw + 16, lane);
            }
            cp_commit();   // one group (empty at t==0)
        }

#pragma unroll
        for (int g = 0; g < 8; g++) {
            if (g == 0) cp_wait0(); else cp_wait1();
            const int op = g >> 2;
            if (vals[op]) {
                if (op == 0)
                    mma_chunk_smemB(acc, (g & 1) ? buf1 : buf0, sW0,
                                    kw + 16 * (g & 3), gi, ti);
                else
                    mma_chunk_regB(acc, (g & 1) ? buf1 : buf0, breg, g & 3, gi, ti);
            }
            const int gn = g + 2;
            if (gn == 4) {   // op1 dependency: h1 flags, own group only
                if (layer == 0) {
                    if (t > 0) spin8(&g_flag[(size_t)(t - 1) * 64 + 8 * w]);
                } else {
                    spin8(&g_flag[(size_t)t * 64 + 8 * w]);
                }
            }
            if (gn < 8) {
                const int opn = gn >> 2;
                if (vals[opn])
                    issue_chunk((gn & 1) ? buf1 : buf0, srcs[opn], strds[opn],
                                kw + 16 * (gn & 3), lane);
            } else if (layer == 0 && t < T_LEN - 1) {
                // carry-over: next step's x chunks 0,1
                issue_chunk((gn & 1) ? buf1 : buf0, g_xr + (size_t)(t + 1) * 512,
                            (size_t)T_LEN * HID, kw + 16 * (gn - 8), lane);
            }
            cp_commit();
        }

        // Write K-split partials (dedicated region; own rows, no sync needed)
#pragma unroll
        for (int mt = 0; mt < 4; mt++) {
#pragma unroll
            for (int nt = 0; nt < 4; nt++) {
                int m = mt * 16 + gi;
                int n = nt * 8 + 2 * ti;
                int base = (w * 64 + m) * PPITCH + n;
                sP[base]     = acc[mt][nt][0];
                sP[base + 1] = acc[mt][nt][1];
                sP[base + 8 * PPITCH]     = acc[mt][nt][2];
                sP[base + 8 * PPITCH + 1] = acc[mt][nt][3];
            }
        }
        __syncthreads();   // S_a: all partials visible

        // Reduce partials + bias + gate math + state update
        float* h_out;
        if (layer == 0)
            h_out = g_hseq + (size_t)t * BH;
        else
            h_out = (t == T_LEN - 1) ? out : (g_h2 + (size_t)(t & 1) * BH);
        const bool final_raw = (layer == 1) && (t == T_LEN - 1);

#pragma unroll
        for (int qq = 0; qq < 2; qq++) {
            int q = tid + (qq << 8);
            int b = q >> 3, j = q & 7;
            float s0 = 0.f, s1 = 0.f, s2 = 0.f, s3 = 0.f;
#pragma unroll
            for (int pw = 0; pw < 8; pw++) {
                int rb = (pw * 64 + b) * PPITCH + j * 4;
                s0 += sP[rb];
                s1 += sP[rb + 1];
                s2 += sP[rb + 2];
                s3 += sP[rb + 3];
            }
            float fg = fsig(s0 + sBias[j * 4 + 0]);
            float ig = fsig(s1 + sBias[j * 4 + 1]);
            float gg = ftanh(s2 + sBias[j * 4 + 2]);
            float og = fsig(s3 + sBias[j * 4 + 3]);
            float c = sC[b * 8 + j];
            c = fg * c + ig * gg;
            sC[b * 8 + j] = c;
            float hv = og * ftanh(c);
            h_out[(size_t)b * HID + (n_blk >> 2) + j] = final_raw ? hv : tfr(hv);
        }

        // S_b then single release store (CG grid-sync publish idiom)
        __syncthreads();
        if (tid == 0) {
            unsigned* p = &g_flag[(size_t)(layer * T_LEN + t) * 64 + bslot];
            asm volatile("st.release.gpu.global.u32 [%0], %1;"
                         :: "l"(p), "r"(1u) : "memory");
        }
    }
}

// ---------------------------------------------------------------------------
// Prep: tf32-round x AND reset flags (2 graph nodes total)
// ---------------------------------------------------------------------------
__global__ void prep(const float4* __restrict__ x) {
    size_t i = (size_t)blockIdx.x * blockDim.x + threadIdx.x;
    if (i < 2 * T_LEN * 64) g_flag[i] = 0;
    float4 v = x[i];
    v.x = tfr(v.x); v.y = tfr(v.y); v.z = tfr(v.z); v.w = tfr(v.w);
    ((float4*)g_xr)[i] = v;
}

// ---------------------------------------------------------------------------
// Launch: 2 graph nodes
// ---------------------------------------------------------------------------
extern "C" void kernel_launch(void* const* d_in, const int* in_sizes, int n_in,
                              void* d_out, int out_size) {
    const float* x   = (const float*)d_in[0];
    const float* Wx0 = (const float*)d_in[1];
    const float* bx0 = (const float*)d_in[2];
    const float* Wh0 = (const float*)d_in[3];
    const float* bh0 = (const float*)d_in[4];
    const float* Wx1 = (const float*)d_in[5];
    const float* bx1 = (const float*)d_in[6];
    const float* Wh1 = (const float*)d_in[7];
    const float* bh1 = (const float*)d_in[8];

    const size_t SMEM_BYTES =
        (size_t)(32 * WPITCH0 + 8 * NBUF * BUFSZ + 8 * 64 * PPITCH + 512 + 32)
        * sizeof(float);
    cudaFuncSetAttribute(lstm_fused, cudaFuncAttributeMaxDynamicSharedMemorySize,
                         (int)SMEM_BYTES);

    prep<<<4096, 1024>>>((const float4*)x);
    lstm_fused<<<128, 256, SMEM_BYTES>>>(Wx0, bx0, Wh0, bh0,
                                         Wx1, bx1, Wh1, bh1, (float*)d_out);
}

// round 9
// speedup vs baseline: 1.6035x; 1.6035x over previous
#include <cuda_runtime.h>
#include <cuda_fp16.h>
#include <math.h>

#define T_LEN 512
#define BATCH 64
#define HID   512
#define BH    (BATCH * HID)
#define WPH   520              // op0 weight pitch (halves): u32-pitch 260 ≡ 4 mod 32
#define BPH   40               // stage pitch (halves): u32-pitch 20 -> conflict-free
#define BUFH  (64 * BPH)       // 2560 halves per chunk buffer (5120 B)
#define NBUF  3                // staging depth per warp
#define PPITCH 33              // partials pitch (floats)

// ---------------------------------------------------------------------------
// Static device scratch
// ---------------------------------------------------------------------------
__device__ __align__(16) __half g_xr[(size_t)BATCH * T_LEN * HID];  // fp16 x
__device__ __align__(16) __half g_hseq[(size_t)T_LEN * BH];         // L0 hidden seq (fp16)
__device__ __align__(16) __half g_h2[2 * BH];                       // L1 hidden dbuf (fp16)
__device__ unsigned g_cnt[2 * T_LEN * 8];                           // per-(layer,step,group)

// ---------------------------------------------------------------------------
// Helpers
// ---------------------------------------------------------------------------
__device__ __forceinline__ unsigned pack2(float lo, float hi) {
    __half2 h = __floats2half2_rn(lo, hi);
    return *reinterpret_cast<unsigned*>(&h);
}

__device__ __forceinline__ void mma_m16n8k16(float c[4], const unsigned a[4], const unsigned b[2]) {
    asm volatile(
        "mma.sync.aligned.m16n8k16.row.col.f32.f16.f16.f32 "
        "{%0,%1,%2,%3}, {%4,%5,%6,%7}, {%8,%9}, {%0,%1,%2,%3};"
        : "+f"(c[0]), "+f"(c[1]), "+f"(c[2]), "+f"(c[3])
        : "r"(a[0]), "r"(a[1]), "r"(a[2]), "r"(a[3]), "r"(b[0]), "r"(b[1]));
}

// Gate-interleaved column n = 4*j + gate -> original weight row r = gate*512 + j
__device__ __forceinline__ int remap_row(int n) { return ((n & 3) << 9) | (n >> 2); }

__device__ __forceinline__ void cp_commit() {
    asm volatile("cp.async.commit_group;" ::: "memory");
}
__device__ __forceinline__ void cp_wait0() { asm volatile("cp.async.wait_group 0;" ::: "memory"); }
__device__ __forceinline__ void cp_wait1() { asm volatile("cp.async.wait_group 1;" ::: "memory"); }
__device__ __forceinline__ void cp_wait2() { asm volatile("cp.async.wait_group 2;" ::: "memory"); }

// Per-warp acquire spin (tight; NO nanosleep — it regressed R7).
__device__ __forceinline__ void spin_ge(unsigned* p, unsigned v) {
    if ((threadIdx.x & 31) == 0) {
        unsigned x;
        do {
            asm volatile("ld.global.acquire.gpu.u32 %0, [%1];" : "=r"(x) : "l"(p));
        } while (x < v);
    }
    __syncwarp();
}

// Issue one warp-private 64x16(half) chunk = 64 rows x 32 B via cp.async.cg.
__device__ __forceinline__ void issue_chunk(__half* buf, const __half* __restrict__ src,
                                            size_t stride, int col0, int lane) {
#pragma unroll
    for (int i = 0; i < 4; i++) {
        int cc = lane + (i << 5);
        int row = cc >> 1, h8 = (cc & 1) << 3;
        const __half* g = src + (size_t)row * stride + col0 + h8;
        unsigned s = (unsigned)__cvta_generic_to_shared(buf + row * BPH + h8);
        asm volatile("cp.async.cg.shared.global [%0], [%1], 16;" :: "r"(s), "l"(g));
    }
}

// Load A-frags for one k16 chunk (m64 rows), fp16: 4 mt x 4 .b32 regs.
__device__ __forceinline__ void load_afr(unsigned afr[4][4], const __half* buf,
                                         int gi, int ti) {
    const unsigned* a32 = (const unsigned*)buf;   // u32 pitch = BPH/2 = 20
#pragma unroll
    for (int mt = 0; mt < 4; mt++) {
        int r = mt * 16;
        afr[mt][0] = a32[(r + gi) * 20 + ti];
        afr[mt][1] = a32[(r + gi + 8) * 20 + ti];
        afr[mt][2] = a32[(r + gi) * 20 + ti + 4];
        afr[mt][3] = a32[(r + gi + 8) * 20 + ti + 4];
    }
}

// MMA over one k16 chunk with B from SMEM (op0 path).
__device__ __forceinline__ void mma_chunk_smemB(float acc[4][4][4], const __half* buf,
                                                const __half* sW0, int kbase,
                                                int gi, int ti) {
    unsigned afr[4][4];
    load_afr(afr, buf, gi, ti);
    const unsigned* w32 = (const unsigned*)sW0;   // u32 pitch = WPH/2 = 260
    int kb = (kbase >> 1) + ti;
#pragma unroll
    for (int nt = 0; nt < 4; nt++) {
        unsigned bfr[2];
        bfr[0] = w32[(nt * 8 + gi) * 260 + kb];
        bfr[1] = w32[(nt * 8 + gi) * 260 + kb + 4];
#pragma unroll
        for (int mt = 0; mt < 4; mt++) mma_m16n8k16(acc[mt][nt], afr[mt], bfr);
    }
}

// MMA over one k16 chunk with B from registers (op1 / critical path).
__device__ __forceinline__ void mma_chunk_regB(float acc[4][4][4], const __half* buf,
                                               const unsigned breg[4][4][2], int u,
                                               int gi, int ti) {
    unsigned afr[4][4];
    load_afr(afr, buf, gi, ti);
#pragma unroll
    for (int nt = 0; nt < 4; nt++)
#pragma unroll
        for (int mt = 0; mt < 4; mt++)
            mma_m16n8k16(acc[mt][nt], afr[mt], breg[nt][u]);
}

__device__ __forceinline__ float fsig(float x) {
    return __fdividef(1.f, 1.f + __expf(-x));
}
__device__ __forceinline__ float ftanh(float x) {
    return 1.f - __fdividef(2.f, __expf(2.f * x) + 1.f);
}

// ---------------------------------------------------------------------------
// Fused dual-layer persistent LSTM (fp16 operands, fp32 accumulate).
// 128 blocks (64/layer), 256 threads (8 warps). Block owns 32 interleaved
// gate cols. Warp w owns K-slice [64w,64w+64) per operand, staged as 4 k16
// chunks through a depth-3 private cp.async pipeline. op1 weights in regs.
// Per-group counters, tight acquire spin, red.release publish (R6 winner).
// ---------------------------------------------------------------------------
extern "C" __global__ void __launch_bounds__(256, 1)
lstm_fused(const float* __restrict__ Wx0, const float* __restrict__ bx0,
           const float* __restrict__ Wh0, const float* __restrict__ bh0,
           const float* __restrict__ Wx1, const float* __restrict__ bx1,
           const float* __restrict__ Wh1, const float* __restrict__ bh1,
           float* __restrict__ out) {
    extern __shared__ __half smem[];
    __half* sW0 = smem;                               // 32*WPH = 16640 halves
    __half* sStage = smem + 32 * WPH;                 // 8*NBUF*BUFH = 61440 halves
    float* sC = (float*)(sStage + 8 * NBUF * BUFH);   // 512 floats
    float* sBias = sC + 512;                          // 32 floats
    float* sP = (float*)sStage;                       // partials alias (67584B <= 122880B)

    const int tid = threadIdx.x;
    const int w = tid >> 5;
    const int lane = tid & 31;
    const int gi = lane >> 2;
    const int ti = lane & 3;
    const int layer = blockIdx.x >> 6;
    const int bslot = blockIdx.x & 63;
    const int n_blk = bslot * 32;
    const int kw = w * 64;                            // warp K-slice base (halves)

    __half* bufs[NBUF];
#pragma unroll
    for (int i = 0; i < NBUF; i++) bufs[i] = sStage + (w * NBUF + i) * BUFH;

    // op0 weight matrix -> SMEM ; op1 weight matrix -> registers
    const float* W0 = layer ? Wh1 : Wx0;   // op0: L0=x·Wx0, L1=h2·Wh1
    const float* W1 = layer ? Wx1 : Wh0;   // op1: L0=h1·Wh0, L1=h1·Wx1
    const float* bxp = layer ? bx1 : bx0;
    const float* bhp = layer ? bh1 : bh0;

    // Stage op0 weights once (remapped rows, fp16)
    for (int v = tid; v < 32 * 128; v += 256) {
        int row = v >> 7, c4 = (v & 127) * 4;
        int r = remap_row(n_blk + row);
        float4 f = *(const float4*)(W0 + (size_t)r * 512 + c4);
        __half2* d = (__half2*)(sW0 + (size_t)row * WPH + c4);
        d[0] = __floats2half2_rn(f.x, f.y);
        d[1] = __floats2half2_rn(f.z, f.w);
    }
    if (tid < 32) {
        int r = remap_row(n_blk + tid);
        sBias[tid] = bxp[r] + bhp[r];
    }
    for (int v = tid; v < 512; v += 256) sC[v] = 0.f;

    // Preload op1 B-fragments (fp16, 32 regs; constant across steps)
    unsigned breg[4][4][2];
#pragma unroll
    for (int nt = 0; nt < 4; nt++) {
        int r = remap_row(n_blk + nt * 8 + gi);
        const float* wr = W1 + (size_t)r * 512 + kw;
#pragma unroll
        for (int u = 0; u < 4; u++) {
            breg[nt][u][0] = pack2(wr[16 * u + 2 * ti], wr[16 * u + 2 * ti + 1]);
            breg[nt][u][1] = pack2(wr[16 * u + 2 * ti + 8], wr[16 * u + 2 * ti + 9]);
        }
    }
    __syncthreads();

    for (int t = 0; t < T_LEN; t++) {
        float acc[4][4][4];
#pragma unroll
        for (int a = 0; a < 4; a++)
#pragma unroll
            for (int b = 0; b < 4; b++)
#pragma unroll
                for (int c = 0; c < 4; c++) acc[a][b][c] = 0.f;

        const __half* srcs[2];
        size_t strds[2];
        bool vals[2];
        if (layer == 0) {
            srcs[0] = g_xr + (size_t)t * 512;            // x[b][t][:]
            strds[0] = (size_t)T_LEN * HID;  vals[0] = true;
            srcs[1] = g_hseq + (size_t)(t - 1) * BH;
            strds[1] = HID;                  vals[1] = (t > 0);
        } else {
            srcs[0] = g_h2 + (size_t)((t + 1) & 1) * BH;
            strds[0] = HID;                  vals[0] = (t > 0);
            srcs[1] = g_hseq + (size_t)t * BH;
            strds[1] = HID;                  vals[1] = true;
        }

        // op0 dependency (layer 1: own cohort, previous step, own group only)
        if (layer == 1 && t > 0)
            spin_ge(&g_cnt[(T_LEN + (t - 1)) * 8 + w], 8u);

        // Pre-issue op0 chunks 0..2 (always commit to keep group counts aligned)
#pragma unroll
        for (int c = 0; c < 3; c++) {
            if (vals[0]) issue_chunk(bufs[c], srcs[0], strds[0], kw + 16 * c, lane);
            cp_commit();
        }

#pragma unroll
        for (int g = 0; g < 8; g++) {
            if (g < 6) cp_wait2(); else if (g == 6) cp_wait1(); else cp_wait0();
            const int op = g >> 2;
            if (vals[op]) {
                if (op == 0)
                    mma_chunk_smemB(acc, bufs[g % NBUF], sW0, kw + 16 * (g & 3), gi, ti);
                else
                    mma_chunk_regB(acc, bufs[g % NBUF], breg, g & 3, gi, ti);
            }
            const int gn = g + 3;
            if (gn < 8) {
                if (gn == 4) {   // op1 dependency (h1), own group only
                    if (layer == 0) {
                        if (t > 0) spin_ge(&g_cnt[(t - 1) * 8 + w], 8u);
                    } else {
                        spin_ge(&g_cnt[t * 8 + w], 8u);
                    }
                }
                const int opn = gn >> 2;
                if (vals[opn])
                    issue_chunk(bufs[gn % NBUF], srcs[opn], strds[opn],
                                kw + 16 * (gn & 3), lane);
                cp_commit();
            }
        }

        __syncthreads();   // all warps done with stage bufs before partials alias

        // Write K-split partials
#pragma unroll
        for (int mt = 0; mt < 4; mt++) {
#pragma unroll
            for (int nt = 0; nt < 4; nt++) {
                int m = mt * 16 + gi;
                int n = nt * 8 + 2 * ti;
                int base = (w * 64 + m) * PPITCH + n;
                sP[base]     = acc[mt][nt][0];
                sP[base + 1] = acc[mt][nt][1];
                sP[base + 8 * PPITCH]     = acc[mt][nt][2];
                sP[base + 8 * PPITCH + 1] = acc[mt][nt][3];
            }
        }
        __syncthreads();

        // Reduce partials + bias + gate math + state update
        __half* h_out_h;
        if (layer == 0)
            h_out_h = g_hseq + (size_t)t * BH;
        else
            h_out_h = g_h2 + (size_t)(t & 1) * BH;
        const bool final_raw = (layer == 1) && (t == T_LEN - 1);

#pragma unroll
        for (int qq = 0; qq < 2; qq++) {
            int q = tid + (qq << 8);
            int b = q >> 3, j = q & 7;
            float s0 = 0.f, s1 = 0.f, s2 = 0.f, s3 = 0.f;
#pragma unroll
            for (int pw = 0; pw < 8; pw++) {
                int rb = (pw * 64 + b) * PPITCH + j * 4;
                s0 += sP[rb];
                s1 += sP[rb + 1];
                s2 += sP[rb + 2];
                s3 += sP[rb + 3];
            }
            float fg = fsig(s0 + sBias[j * 4 + 0]);
            float ig = fsig(s1 + sBias[j * 4 + 1]);
            float gg = ftanh(s2 + sBias[j * 4 + 2]);
            float og = fsig(s3 + sBias[j * 4 + 3]);
            float c = sC[b * 8 + j];
            c = fg * c + ig * gg;
            sC[b * 8 + j] = c;
            float hv = og * ftanh(c);
            int col = (n_blk >> 2) + j;
            if (final_raw) out[(size_t)b * HID + col] = hv;
            else           h_out_h[(size_t)b * HID + col] = __float2half_rn(hv);
        }

        // Publish: block-sync then ONE release-reduction
        __syncthreads();
        if (tid == 0) {
            unsigned* p = &g_cnt[((layer * T_LEN) + t) * 8 + (bslot >> 3)];
            asm volatile("red.release.gpu.global.add.u32 [%0], %1;"
                         :: "l"(p), "r"(1u) : "memory");
        }
    }
}

// ---------------------------------------------------------------------------
// Prep: fp16-convert x AND reset counters (2 graph nodes total)
// ---------------------------------------------------------------------------
__global__ void prep(const float4* __restrict__ x) {
    size_t i = (size_t)blockIdx.x * blockDim.x + threadIdx.x;
    if (i < 2 * T_LEN * 8) g_cnt[i] = 0;
    float4 v = x[i];
    __half2* dst = (__half2*)g_xr;
    dst[i * 2]     = __floats2half2_rn(v.x, v.y);
    dst[i * 2 + 1] = __floats2half2_rn(v.z, v.w);
}

// ---------------------------------------------------------------------------
// Launch: 2 graph nodes
// ---------------------------------------------------------------------------
extern "C" void kernel_launch(void* const* d_in, const int* in_sizes, int n_in,
                              void* d_out, int out_size) {
    const float* x   = (const float*)d_in[0];
    const float* Wx0 = (const float*)d_in[1];
    const float* bx0 = (const float*)d_in[2];
    const float* Wh0 = (const float*)d_in[3];
    const float* bh0 = (const float*)d_in[4];
    const float* Wx1 = (const float*)d_in[5];
    const float* bx1 = (const float*)d_in[6];
    const float* Wh1 = (const float*)d_in[7];
    const float* bh1 = (const float*)d_in[8];

    const size_t SMEM_BYTES =
        (size_t)(32 * WPH + 8 * NBUF * BUFH) * sizeof(__half)
        + (512 + 32) * sizeof(float);
    cudaFuncSetAttribute(lstm_fused, cudaFuncAttributeMaxDynamicSharedMemorySize,
                         (int)SMEM_BYTES);

    prep<<<4096, 1024>>>((const float4*)x);
    lstm_fused<<<128, 256, SMEM_BYTES>>>(Wx0, bx0, Wh0, bh0,
                                         Wx1, bx1, Wh1, bh1, (float*)d_out);
}